// round 5
// baseline (speedup 1.0000x reference)
#include <cuda_runtime.h>
#include <cuda_bf16.h>

#define N_NODES 100000
#define N_EDGES 1200000
#define FDIM 64
#define NB_SCAN ((N_NODES + 1023) / 1024)   // 98

// ---------------- scratch (device globals; no allocation allowed) -------------
__device__ int   g_is64;
__device__ int   g_degs[N_NODES];          // out-degree of src (row) -> norm
__device__ int   g_degd[N_NODES];          // in-degree of dst (for CSR)
__device__ int   g_rowptr[N_NODES + 1];
__device__ int   g_cursor[N_NODES];
__device__ int   g_bsum[NB_SCAN];
__device__ int2  g_edge[N_EDGES];          // (src, norm-as-int) grouped by dst
__device__ float g_tx1[N_NODES * FDIM];
__device__ float g_p2 [N_NODES * FDIM];
__device__ float g_hA [N_NODES * FDIM];
__device__ float g_hB [N_NODES * FDIM];
__device__ float g_Wp [3][3 * FDIM * FDIM];  // transformed weights per layer

// ---------------- init: zero degrees + dtype detection ------------------------
// int64 edge_index (values < 2^31) has all-zero odd 32-bit words.
__global__ void init_kernel(const int* __restrict__ ei32) {
    int i = blockIdx.x * blockDim.x + threadIdx.x;
    if (i < N_NODES) { g_degs[i] = 0; g_degd[i] = 0; }
    if (i == 0) {
        int odd_zero = 1;
        for (int k = 0; k < 512; k++)
            if (ei32[2 * k + 1] != 0) { odd_zero = 0; break; }
        g_is64 = odd_zero;
    }
}

__device__ __forceinline__ void load_edge(const void* ei, int e, int& s, int& d) {
    if (g_is64) {
        const long long* p = (const long long*)ei;
        s = (int)p[e]; d = (int)p[N_EDGES + e];
    } else {
        const int* p = (const int*)ei;
        s = p[e]; d = p[N_EDGES + e];
    }
    if ((unsigned)s >= N_NODES || (unsigned)d >= N_NODES) { s = 0; d = 0; }
}

// count src out-degree and dst in-degree
__global__ void count_kernel(const void* __restrict__ ei) {
    int e = blockIdx.x * blockDim.x + threadIdx.x;
    if (e >= N_EDGES) return;
    int s, d;
    load_edge(ei, e, s, d);
    atomicAdd(&g_degs[s], 1);
    atomicAdd(&g_degd[d], 1);
}

// ---- CSR build: exclusive scan of g_degd into g_rowptr ----------------------
__global__ __launch_bounds__(1024) void scan1_kernel() {
    __shared__ int s[1024];
    int tid = threadIdx.x;
    int i = blockIdx.x * 1024 + tid;
    int v = (i < N_NODES) ? g_degd[i] : 0;
    s[tid] = v;
    __syncthreads();
    for (int off = 1; off < 1024; off <<= 1) {
        int t = (tid >= off) ? s[tid - off] : 0;
        __syncthreads();
        s[tid] += t;
        __syncthreads();
    }
    int incl = s[tid];
    if (i < N_NODES) g_rowptr[i] = incl - v;
    if (tid == 1023) g_bsum[blockIdx.x] = incl;
}

__global__ __launch_bounds__(128) void scan2_kernel() {
    __shared__ int sh[128];
    int tid = threadIdx.x;
    int v = (tid < NB_SCAN) ? g_bsum[tid] : 0;
    sh[tid] = v;
    __syncthreads();
    for (int off = 1; off < 128; off <<= 1) {
        int t = (tid >= off) ? sh[tid - off] : 0;
        __syncthreads();
        sh[tid] += t;
        __syncthreads();
    }
    if (tid < NB_SCAN) g_bsum[tid] = sh[tid] - v;   // exclusive
    if (tid == 0) g_rowptr[N_NODES] = N_EDGES;
}

__global__ void scan3_kernel() {
    int i = blockIdx.x * blockDim.x + threadIdx.x;
    if (i >= N_NODES) return;
    int v = g_rowptr[i] + g_bsum[i >> 10];
    g_rowptr[i] = v;
    g_cursor[i] = v;
}

// scatter edges into CSR slots; norm = -rsqrt(degs[s]*degs[d]) computed here
__global__ void fill_kernel(const void* __restrict__ ei) {
    int e = blockIdx.x * blockDim.x + threadIdx.x;
    if (e >= N_EDGES) return;
    int s, d;
    load_edge(ei, e, s, d);
    int pos = atomicAdd(&g_cursor[d], 1);
    int pd = g_degs[s] * g_degs[d];
    float nv = (pd > 0) ? -rsqrtf((float)pd) : 0.0f;
    g_edge[pos] = make_int2(s, __float_as_int(nv));
}

// ---- weight pre-transform: W0' = W0 - W2, W1' = W1, W2' = 2*W2 --------------
__global__ void wprep_kernel(const float* __restrict__ W) {
    int i = blockIdx.x * blockDim.x + threadIdx.x;
    if (i >= 3 * 3 * 4096) return;
    int layer = i / 12288, rem = i % 12288;
    int t = rem / 4096, idx = rem % 4096;
    const float* Wl = W + layer * 12288;
    float v;
    if (t == 0)      v = Wl[idx] - Wl[2 * 4096 + idx];
    else if (t == 1) v = Wl[4096 + idx];
    else             v = 2.0f * Wl[2 * 4096 + idx];
    g_Wp[layer][t * 4096 + idx] = v;
}

// ---------------- pull-mode propagate (unrolled x8 for MLP) ------------------
// 16 lanes per node, float4 per lane. out[n] = sum_e norm_e * in[src_e].
__global__ __launch_bounds__(256, 4) void pull_kernel(const float* __restrict__ in,
                                                      float* __restrict__ out) {
    int t = blockIdx.x * 256 + threadIdx.x;
    int node = t >> 4;
    int lane = t & 15;
    if (node >= N_NODES) return;
    int e   = __ldg(&g_rowptr[node]);
    int end = __ldg(&g_rowptr[node + 1]);
    float4 acc = make_float4(0.f, 0.f, 0.f, 0.f);

    while (e + 8 <= end) {
        int2   ed[8];
        float4 v[8];
#pragma unroll
        for (int i = 0; i < 8; i++) ed[i] = __ldg(&g_edge[e + i]);
#pragma unroll
        for (int i = 0; i < 8; i++)
            v[i] = __ldg((const float4*)(in + ed[i].x * FDIM + lane * 4));
#pragma unroll
        for (int i = 0; i < 8; i++) {
            float n = __int_as_float(ed[i].y);
            acc.x = fmaf(n, v[i].x, acc.x);
            acc.y = fmaf(n, v[i].y, acc.y);
            acc.z = fmaf(n, v[i].z, acc.z);
            acc.w = fmaf(n, v[i].w, acc.w);
        }
        e += 8;
    }
    if (e + 4 <= end) {
        int2   ed[4];
        float4 v[4];
#pragma unroll
        for (int i = 0; i < 4; i++) ed[i] = __ldg(&g_edge[e + i]);
#pragma unroll
        for (int i = 0; i < 4; i++)
            v[i] = __ldg((const float4*)(in + ed[i].x * FDIM + lane * 4));
#pragma unroll
        for (int i = 0; i < 4; i++) {
            float n = __int_as_float(ed[i].y);
            acc.x = fmaf(n, v[i].x, acc.x);
            acc.y = fmaf(n, v[i].y, acc.y);
            acc.z = fmaf(n, v[i].z, acc.z);
            acc.w = fmaf(n, v[i].w, acc.w);
        }
        e += 4;
    }
#pragma unroll 1
    for (; e < end; e++) {
        int2 ed = __ldg(&g_edge[e]);
        float nv = __int_as_float(ed.y);
        float4 v = __ldg((const float4*)(in + ed.x * FDIM + lane * 4));
        acc.x = fmaf(nv, v.x, acc.x); acc.y = fmaf(nv, v.y, acc.y);
        acc.z = fmaf(nv, v.z, acc.z); acc.w = fmaf(nv, v.w, acc.w);
    }
    *(float4*)(out + node * FDIM + lane * 4) = acc;
}

// ---------------- fused 3-way GEMM (FFMA2, 2 rows/thread) --------------------
__device__ __forceinline__ void fma2(unsigned long long& acc,
                                     unsigned long long w,
                                     unsigned long long a) {
    asm("fma.rn.f32x2 %0, %1, %2, %0;" : "+l"(acc) : "l"(w), "l"(a));
}
__device__ __forceinline__ unsigned long long splat2(float f) {
    unsigned long long r;
    asm("mov.b64 %0, {%1, %1};" : "=l"(r) : "f"(f));
    return r;
}

__global__ __launch_bounds__(256) void gemm_epi_kernel(
    const float* __restrict__ t0, const float* __restrict__ t1,
    const float* __restrict__ p2, const float* __restrict__ Wp,
    const float* __restrict__ bias, const float* __restrict__ skip,
    float* __restrict__ out) {
    __shared__ float sW[3 * FDIM * FDIM];  // 48 KB

    for (int i = threadIdx.x; i < 3 * FDIM * FDIM / 4; i += 256)
        ((float4*)sW)[i] = ((const float4*)Wp)[i];
    __syncthreads();

    int base = blockIdx.x * 128;
    int rg = threadIdx.x >> 2;
    int q  = threadIdx.x & 3;
    int jb = q * 16;
    int rA = base + rg;
    int rB = base + rg + 64;
    bool okA = rA < N_NODES, okB = rB < N_NODES;
    if (!okA) return;

    const float* a0 = t0 + rA * FDIM;  const float* a1 = t1 + rA * FDIM;
    const float* a2p = p2 + rA * FDIM;
    const float* b0 = t0 + rB * FDIM;  const float* b1 = t1 + rB * FDIM;
    const float* b2p = p2 + rB * FDIM;

    unsigned long long accA[8], accB[8];
#pragma unroll
    for (int i = 0; i < 8; i++) { accA[i] = 0ULL; accB[i] = 0ULL; }

#pragma unroll 2
    for (int kk = 0; kk < FDIM; kk += 4) {
        float4 xa0 = __ldg((const float4*)(a0 + kk));
        float4 xa1 = __ldg((const float4*)(a1 + kk));
        float4 xa2 = __ldg((const float4*)(a2p + kk));
        float4 xb0, xb1, xb2;
        if (okB) {
            xb0 = __ldg((const float4*)(b0 + kk));
            xb1 = __ldg((const float4*)(b1 + kk));
            xb2 = __ldg((const float4*)(b2p + kk));
        } else {
            xb0 = xb1 = xb2 = make_float4(0.f, 0.f, 0.f, 0.f);
        }
        float fa0[4] = {xa0.x, xa0.y, xa0.z, xa0.w};
        float fa1[4] = {xa1.x, xa1.y, xa1.z, xa1.w};
        float fa2[4] = {xa2.x, xa2.y, xa2.z, xa2.w};
        float fb0[4] = {xb0.x, xb0.y, xb0.z, xb0.w};
        float fb1[4] = {xb1.x, xb1.y, xb1.z, xb1.w};
        float fb2[4] = {xb2.x, xb2.y, xb2.z, xb2.w};
#pragma unroll
        for (int u = 0; u < 4; u++) {
            int k = kk + u;
            const ulonglong2* w0 = (const ulonglong2*)(sW + k * FDIM + jb);
            const ulonglong2* w1 = (const ulonglong2*)(sW + 4096 + k * FDIM + jb);
            const ulonglong2* w2 = (const ulonglong2*)(sW + 8192 + k * FDIM + jb);
            {
                unsigned long long sA = splat2(fa0[u]), sB = splat2(fb0[u]);
#pragma unroll
                for (int p = 0; p < 4; p++) {
                    ulonglong2 w = w0[p];
                    fma2(accA[2 * p], w.x, sA); fma2(accA[2 * p + 1], w.y, sA);
                    fma2(accB[2 * p], w.x, sB); fma2(accB[2 * p + 1], w.y, sB);
                }
            }
            {
                unsigned long long sA = splat2(fa1[u]), sB = splat2(fb1[u]);
#pragma unroll
                for (int p = 0; p < 4; p++) {
                    ulonglong2 w = w1[p];
                    fma2(accA[2 * p], w.x, sA); fma2(accA[2 * p + 1], w.y, sA);
                    fma2(accB[2 * p], w.x, sB); fma2(accB[2 * p + 1], w.y, sB);
                }
            }
            {
                unsigned long long sA = splat2(fa2[u]), sB = splat2(fb2[u]);
#pragma unroll
                for (int p = 0; p < 4; p++) {
                    ulonglong2 w = w2[p];
                    fma2(accA[2 * p], w.x, sA); fma2(accA[2 * p + 1], w.y, sA);
                    fma2(accB[2 * p], w.x, sB); fma2(accB[2 * p + 1], w.y, sB);
                }
            }
        }
    }

    float bia[16];
#pragma unroll
    for (int j = 0; j < 16; j++) bia[j] = bias[jb + j];

    {
        float o[16];
#pragma unroll
        for (int i = 0; i < 8; i++) {
            float f0, f1;
            asm("mov.b64 {%0, %1}, %2;" : "=f"(f0), "=f"(f1) : "l"(accA[i]));
            o[2 * i] = f0; o[2 * i + 1] = f1;
        }
#pragma unroll
        for (int j = 0; j < 16; j++) {
            float v = o[j] + bia[j];
            if (skip) v += skip[rA * FDIM + jb + j];
            o[j] = fmaxf(v, 0.f);
        }
#pragma unroll
        for (int p = 0; p < 4; p++)
            *(float4*)(out + rA * FDIM + jb + 4 * p) =
                make_float4(o[4*p], o[4*p+1], o[4*p+2], o[4*p+3]);
    }
    if (okB) {
        float o[16];
#pragma unroll
        for (int i = 0; i < 8; i++) {
            float f0, f1;
            asm("mov.b64 {%0, %1}, %2;" : "=f"(f0), "=f"(f1) : "l"(accB[i]));
            o[2 * i] = f0; o[2 * i + 1] = f1;
        }
#pragma unroll
        for (int j = 0; j < 16; j++) {
            float v = o[j] + bia[j];
            if (skip) v += skip[rB * FDIM + jb + j];
            o[j] = fmaxf(v, 0.f);
        }
#pragma unroll
        for (int p = 0; p < 4; p++)
            *(float4*)(out + rB * FDIM + jb + 4 * p) =
                make_float4(o[4*p], o[4*p+1], o[4*p+2], o[4*p+3]);
    }
}

// ---------------- launch orchestration ---------------------------------------
static inline int cdiv(long long a, long long b) { return (int)((a + b - 1) / b); }

extern "C" void kernel_launch(void* const* d_in, const int* in_sizes, int n_in,
                              void* d_out, int out_size) {
    const float* x  = (const float*)d_in[0];      // [100000, 64]
    const void*  ei = d_in[1];                    // [2, 1200000] int32 or int64
    const float* W  = (const float*)d_in[2];      // [3, 3, 64, 64]
    const float* b  = (const float*)d_in[3];      // [3, 64]
    float*       out = (float*)d_out;             // [100000, 64]

    float *tx1, *p2, *hA, *hB, *Wp0;
    cudaGetSymbolAddress((void**)&tx1, g_tx1);
    cudaGetSymbolAddress((void**)&p2,  g_p2);
    cudaGetSymbolAddress((void**)&hA,  g_hA);
    cudaGetSymbolAddress((void**)&hB,  g_hB);
    cudaGetSymbolAddress((void**)&Wp0, g_Wp);

    // ---- graph prep: zero+detect, degrees, CSR (counting sort), weights ----
    init_kernel<<<cdiv(N_NODES, 256), 256>>>((const int*)ei);
    count_kernel<<<cdiv(N_EDGES, 256), 256>>>(ei);
    scan1_kernel<<<NB_SCAN, 1024>>>();
    scan2_kernel<<<1, 128>>>();
    scan3_kernel<<<cdiv(N_NODES, 256), 256>>>();
    fill_kernel<<<cdiv(N_EDGES, 256), 256>>>(ei);
    wprep_kernel<<<cdiv(3 * 3 * 4096, 256), 256>>>(W);

    const int pull_grid = cdiv((long long)N_NODES * 16, 256);
    const int gemm_grid = cdiv(N_NODES, 128);

    // ---- layer 0: inp = x -> hA (no skip) ----
    pull_kernel<<<pull_grid, 256>>>(x, tx1);
    pull_kernel<<<pull_grid, 256>>>(tx1, p2);
    gemm_epi_kernel<<<gemm_grid, 256>>>(x, tx1, p2, Wp0, b, nullptr, hA);

    // ---- layer 1: inp = hA -> hB (skip = hA) ----
    pull_kernel<<<pull_grid, 256>>>(hA, tx1);
    pull_kernel<<<pull_grid, 256>>>(tx1, p2);
    gemm_epi_kernel<<<gemm_grid, 256>>>(hA, tx1, p2, Wp0 + 3 * 4096,
                                        b + FDIM, hA, hB);

    // ---- layer 2: inp = hB -> d_out (skip = hB) ----
    pull_kernel<<<pull_grid, 256>>>(hB, tx1);
    pull_kernel<<<pull_grid, 256>>>(tx1, p2);
    gemm_epi_kernel<<<gemm_grid, 256>>>(hB, tx1, p2, Wp0 + 6 * 4096,
                                        b + 2 * FDIM, hB, out);
}

// round 6
// speedup vs baseline: 1.0532x; 1.0532x over previous
#include <cuda_runtime.h>
#include <cuda_bf16.h>

#define N_NODES 100000
#define N_EDGES 1200000
#define FDIM 64
#define NB_SCAN ((N_NODES + 1023) / 1024)   // 98

// ---------------- scratch (device globals; no allocation allowed) -------------
__device__ int   g_is64;
__device__ int   g_degs[N_NODES];          // out-degree of src (row) -> norm
__device__ int   g_degd[N_NODES];          // in-degree of dst (for CSR)
__device__ int   g_rowptr[N_NODES + 1];
__device__ int   g_cursor[N_NODES];
__device__ int   g_bsum[NB_SCAN];
__device__ int2  g_edge[N_EDGES];          // (src, norm-as-int) grouped by dst
__device__ float g_tx1[N_NODES * FDIM];
__device__ float g_p2 [N_NODES * FDIM];
__device__ float g_hA [N_NODES * FDIM];
__device__ float g_hB [N_NODES * FDIM];
__device__ float g_Wp [3][3 * FDIM * FDIM];  // transformed weights per layer

// ---------------- init: zero degrees + dtype detection ------------------------
__global__ void init_kernel(const int* __restrict__ ei32) {
    int i = blockIdx.x * blockDim.x + threadIdx.x;
    if (i < N_NODES) { g_degs[i] = 0; g_degd[i] = 0; }
    if (i == 0) {
        int odd_zero = 1;
        for (int k = 0; k < 512; k++)
            if (ei32[2 * k + 1] != 0) { odd_zero = 0; break; }
        g_is64 = odd_zero;
    }
}

__device__ __forceinline__ void load_edge(const void* ei, int e, int& s, int& d) {
    if (g_is64) {
        const long long* p = (const long long*)ei;
        s = (int)p[e]; d = (int)p[N_EDGES + e];
    } else {
        const int* p = (const int*)ei;
        s = p[e]; d = p[N_EDGES + e];
    }
    if ((unsigned)s >= N_NODES || (unsigned)d >= N_NODES) { s = 0; d = 0; }
}

__global__ void count_kernel(const void* __restrict__ ei) {
    int e = blockIdx.x * blockDim.x + threadIdx.x;
    if (e >= N_EDGES) return;
    int s, d;
    load_edge(ei, e, s, d);
    atomicAdd(&g_degs[s], 1);
    atomicAdd(&g_degd[d], 1);
}

// ---- CSR build: exclusive scan of g_degd into g_rowptr ----------------------
__global__ __launch_bounds__(1024) void scan1_kernel() {
    __shared__ int s[1024];
    int tid = threadIdx.x;
    int i = blockIdx.x * 1024 + tid;
    int v = (i < N_NODES) ? g_degd[i] : 0;
    s[tid] = v;
    __syncthreads();
    for (int off = 1; off < 1024; off <<= 1) {
        int t = (tid >= off) ? s[tid - off] : 0;
        __syncthreads();
        s[tid] += t;
        __syncthreads();
    }
    int incl = s[tid];
    if (i < N_NODES) g_rowptr[i] = incl - v;
    if (tid == 1023) g_bsum[blockIdx.x] = incl;
}

__global__ __launch_bounds__(128) void scan2_kernel() {
    __shared__ int sh[128];
    int tid = threadIdx.x;
    int v = (tid < NB_SCAN) ? g_bsum[tid] : 0;
    sh[tid] = v;
    __syncthreads();
    for (int off = 1; off < 128; off <<= 1) {
        int t = (tid >= off) ? sh[tid - off] : 0;
        __syncthreads();
        sh[tid] += t;
        __syncthreads();
    }
    if (tid < NB_SCAN) g_bsum[tid] = sh[tid] - v;   // exclusive
    if (tid == 0) g_rowptr[N_NODES] = N_EDGES;
}

__global__ void scan3_kernel() {
    int i = blockIdx.x * blockDim.x + threadIdx.x;
    if (i >= N_NODES) return;
    int v = g_rowptr[i] + g_bsum[i >> 10];
    g_rowptr[i] = v;
    g_cursor[i] = v;
}

// scatter edges into CSR slots; norm = -rsqrt(degs[s]*degs[d]) computed here
__global__ void fill_kernel(const void* __restrict__ ei) {
    int e = blockIdx.x * blockDim.x + threadIdx.x;
    if (e >= N_EDGES) return;
    int s, d;
    load_edge(ei, e, s, d);
    int pos = atomicAdd(&g_cursor[d], 1);
    int pd = g_degs[s] * g_degs[d];
    float nv = (pd > 0) ? -rsqrtf((float)pd) : 0.0f;
    g_edge[pos] = make_int2(s, __float_as_int(nv));
}

// ---- weight pre-transform: W0' = W0 - W2, W1' = W1, W2' = 2*W2 --------------
__global__ void wprep_kernel(const float* __restrict__ W) {
    int i = blockIdx.x * blockDim.x + threadIdx.x;
    if (i >= 3 * 3 * 4096) return;
    int layer = i / 12288, rem = i % 12288;
    int t = rem / 4096, idx = rem % 4096;
    const float* Wl = W + layer * 12288;
    float v;
    if (t == 0)      v = Wl[idx] - Wl[2 * 4096 + idx];
    else if (t == 1) v = Wl[4096 + idx];
    else             v = 2.0f * Wl[2 * 4096 + idx];
    g_Wp[layer][t * 4096 + idx] = v;
}

// ---------------- pull-mode propagate: software-pipelined batches of 4 --------
// 16 lanes per node, float4 per lane. out[n] = sum_e norm_e * in[src_e].
// Prefetch next edge batch while current gathers are in flight. Predicated
// lanes past `end` gather row 0 (hot line) with norm 0 — no serial tail.
__global__ __launch_bounds__(256) void pull_kernel(const float* __restrict__ in,
                                                   float* __restrict__ out) {
    int t = blockIdx.x * 256 + threadIdx.x;
    int node = t >> 4;
    int lane = t & 15;
    if (node >= N_NODES) return;
    int e   = __ldg(&g_rowptr[node]);
    int end = __ldg(&g_rowptr[node + 1]);
    float4 acc = make_float4(0.f, 0.f, 0.f, 0.f);

    if (e < end) {
        int2 ed[4];
        int last = end - 1;
#pragma unroll
        for (int i = 0; i < 4; i++)
            ed[i] = __ldg(&g_edge[min(e + i, last)]);

        while (true) {
            // issue current gathers (predicated: clamped lanes read row 0, n=0)
            float  n[4];
            float4 v[4];
#pragma unroll
            for (int i = 0; i < 4; i++) {
                bool valid = (e + i < end);
                n[i] = valid ? __int_as_float(ed[i].y) : 0.f;
                int src = valid ? ed[i].x : 0;
                v[i] = __ldg((const float4*)(in + src * FDIM + lane * 4));
            }
            int enext = e + 4;
            // prefetch next edge batch while gathers are outstanding
            int2 ed2[4];
            bool more = (enext < end);
            if (more) {
#pragma unroll
                for (int i = 0; i < 4; i++)
                    ed2[i] = __ldg(&g_edge[min(enext + i, last)]);
            }
#pragma unroll
            for (int i = 0; i < 4; i++) {
                acc.x = fmaf(n[i], v[i].x, acc.x);
                acc.y = fmaf(n[i], v[i].y, acc.y);
                acc.z = fmaf(n[i], v[i].z, acc.z);
                acc.w = fmaf(n[i], v[i].w, acc.w);
            }
            if (!more) break;
            e = enext;
#pragma unroll
            for (int i = 0; i < 4; i++) ed[i] = ed2[i];
        }
    }
    *(float4*)(out + node * FDIM + lane * 4) = acc;
}

// ---------------- fused 3-way GEMM (FFMA2, 2 rows/thread) --------------------
__device__ __forceinline__ void fma2(unsigned long long& acc,
                                     unsigned long long w,
                                     unsigned long long a) {
    asm("fma.rn.f32x2 %0, %1, %2, %0;" : "+l"(acc) : "l"(w), "l"(a));
}
__device__ __forceinline__ unsigned long long splat2(float f) {
    unsigned long long r;
    asm("mov.b64 %0, {%1, %1};" : "=l"(r) : "f"(f));
    return r;
}

__global__ __launch_bounds__(256) void gemm_epi_kernel(
    const float* __restrict__ t0, const float* __restrict__ t1,
    const float* __restrict__ p2, const float* __restrict__ Wp,
    const float* __restrict__ bias, const float* __restrict__ skip,
    float* __restrict__ out) {
    __shared__ float sW[3 * FDIM * FDIM];  // 48 KB

    for (int i = threadIdx.x; i < 3 * FDIM * FDIM / 4; i += 256)
        ((float4*)sW)[i] = ((const float4*)Wp)[i];
    __syncthreads();

    int base = blockIdx.x * 128;
    int rg = threadIdx.x >> 2;
    int q  = threadIdx.x & 3;
    int jb = q * 16;
    int rA = base + rg;
    int rB = base + rg + 64;
    bool okA = rA < N_NODES, okB = rB < N_NODES;
    if (!okA) return;

    const float* a0 = t0 + rA * FDIM;  const float* a1 = t1 + rA * FDIM;
    const float* a2p = p2 + rA * FDIM;
    const float* b0 = t0 + rB * FDIM;  const float* b1 = t1 + rB * FDIM;
    const float* b2p = p2 + rB * FDIM;

    unsigned long long accA[8], accB[8];
#pragma unroll
    for (int i = 0; i < 8; i++) { accA[i] = 0ULL; accB[i] = 0ULL; }

#pragma unroll 2
    for (int kk = 0; kk < FDIM; kk += 4) {
        float4 xa0 = __ldg((const float4*)(a0 + kk));
        float4 xa1 = __ldg((const float4*)(a1 + kk));
        float4 xa2 = __ldg((const float4*)(a2p + kk));
        float4 xb0, xb1, xb2;
        if (okB) {
            xb0 = __ldg((const float4*)(b0 + kk));
            xb1 = __ldg((const float4*)(b1 + kk));
            xb2 = __ldg((const float4*)(b2p + kk));
        } else {
            xb0 = xb1 = xb2 = make_float4(0.f, 0.f, 0.f, 0.f);
        }
        float fa0[4] = {xa0.x, xa0.y, xa0.z, xa0.w};
        float fa1[4] = {xa1.x, xa1.y, xa1.z, xa1.w};
        float fa2[4] = {xa2.x, xa2.y, xa2.z, xa2.w};
        float fb0[4] = {xb0.x, xb0.y, xb0.z, xb0.w};
        float fb1[4] = {xb1.x, xb1.y, xb1.z, xb1.w};
        float fb2[4] = {xb2.x, xb2.y, xb2.z, xb2.w};
#pragma unroll
        for (int u = 0; u < 4; u++) {
            int k = kk + u;
            const ulonglong2* w0 = (const ulonglong2*)(sW + k * FDIM + jb);
            const ulonglong2* w1 = (const ulonglong2*)(sW + 4096 + k * FDIM + jb);
            const ulonglong2* w2 = (const ulonglong2*)(sW + 8192 + k * FDIM + jb);
            {
                unsigned long long sA = splat2(fa0[u]), sB = splat2(fb0[u]);
#pragma unroll
                for (int p = 0; p < 4; p++) {
                    ulonglong2 w = w0[p];
                    fma2(accA[2 * p], w.x, sA); fma2(accA[2 * p + 1], w.y, sA);
                    fma2(accB[2 * p], w.x, sB); fma2(accB[2 * p + 1], w.y, sB);
                }
            }
            {
                unsigned long long sA = splat2(fa1[u]), sB = splat2(fb1[u]);
#pragma unroll
                for (int p = 0; p < 4; p++) {
                    ulonglong2 w = w1[p];
                    fma2(accA[2 * p], w.x, sA); fma2(accA[2 * p + 1], w.y, sA);
                    fma2(accB[2 * p], w.x, sB); fma2(accB[2 * p + 1], w.y, sB);
                }
            }
            {
                unsigned long long sA = splat2(fa2[u]), sB = splat2(fb2[u]);
#pragma unroll
                for (int p = 0; p < 4; p++) {
                    ulonglong2 w = w2[p];
                    fma2(accA[2 * p], w.x, sA); fma2(accA[2 * p + 1], w.y, sA);
                    fma2(accB[2 * p], w.x, sB); fma2(accB[2 * p + 1], w.y, sB);
                }
            }
        }
    }

    float bia[16];
#pragma unroll
    for (int j = 0; j < 16; j++) bia[j] = bias[jb + j];

    {
        float o[16];
#pragma unroll
        for (int i = 0; i < 8; i++) {
            float f0, f1;
            asm("mov.b64 {%0, %1}, %2;" : "=f"(f0), "=f"(f1) : "l"(accA[i]));
            o[2 * i] = f0; o[2 * i + 1] = f1;
        }
#pragma unroll
        for (int j = 0; j < 16; j++) {
            float v = o[j] + bia[j];
            if (skip) v += skip[rA * FDIM + jb + j];
            o[j] = fmaxf(v, 0.f);
        }
#pragma unroll
        for (int p = 0; p < 4; p++)
            *(float4*)(out + rA * FDIM + jb + 4 * p) =
                make_float4(o[4*p], o[4*p+1], o[4*p+2], o[4*p+3]);
    }
    if (okB) {
        float o[16];
#pragma unroll
        for (int i = 0; i < 8; i++) {
            float f0, f1;
            asm("mov.b64 {%0, %1}, %2;" : "=f"(f0), "=f"(f1) : "l"(accB[i]));
            o[2 * i] = f0; o[2 * i + 1] = f1;
        }
#pragma unroll
        for (int j = 0; j < 16; j++) {
            float v = o[j] + bia[j];
            if (skip) v += skip[rB * FDIM + jb + j];
            o[j] = fmaxf(v, 0.f);
        }
#pragma unroll
        for (int p = 0; p < 4; p++)
            *(float4*)(out + rB * FDIM + jb + 4 * p) =
                make_float4(o[4*p], o[4*p+1], o[4*p+2], o[4*p+3]);
    }
}

// ---------------- launch orchestration ---------------------------------------
static inline int cdiv(long long a, long long b) { return (int)((a + b - 1) / b); }

extern "C" void kernel_launch(void* const* d_in, const int* in_sizes, int n_in,
                              void* d_out, int out_size) {
    const float* x  = (const float*)d_in[0];      // [100000, 64]
    const void*  ei = d_in[1];                    // [2, 1200000] int32 or int64
    const float* W  = (const float*)d_in[2];      // [3, 3, 64, 64]
    const float* b  = (const float*)d_in[3];      // [3, 64]
    float*       out = (float*)d_out;             // [100000, 64]

    float *tx1, *p2, *hA, *hB, *Wp0;
    cudaGetSymbolAddress((void**)&tx1, g_tx1);
    cudaGetSymbolAddress((void**)&p2,  g_p2);
    cudaGetSymbolAddress((void**)&hA,  g_hA);
    cudaGetSymbolAddress((void**)&hB,  g_hB);
    cudaGetSymbolAddress((void**)&Wp0, g_Wp);

    // ---- graph prep: zero+detect, degrees, CSR (counting sort), weights ----
    init_kernel<<<cdiv(N_NODES, 256), 256>>>((const int*)ei);
    count_kernel<<<cdiv(N_EDGES, 256), 256>>>(ei);
    scan1_kernel<<<NB_SCAN, 1024>>>();
    scan2_kernel<<<1, 128>>>();
    scan3_kernel<<<cdiv(N_NODES, 256), 256>>>();
    fill_kernel<<<cdiv(N_EDGES, 256), 256>>>(ei);
    wprep_kernel<<<cdiv(3 * 3 * 4096, 256), 256>>>(W);

    const int pull_grid = cdiv((long long)N_NODES * 16, 256);
    const int gemm_grid = cdiv(N_NODES, 128);

    // ---- layer 0: inp = x -> hA (no skip) ----
    pull_kernel<<<pull_grid, 256>>>(x, tx1);
    pull_kernel<<<pull_grid, 256>>>(tx1, p2);
    gemm_epi_kernel<<<gemm_grid, 256>>>(x, tx1, p2, Wp0, b, nullptr, hA);

    // ---- layer 1: inp = hA -> hB (skip = hA) ----
    pull_kernel<<<pull_grid, 256>>>(hA, tx1);
    pull_kernel<<<pull_grid, 256>>>(tx1, p2);
    gemm_epi_kernel<<<gemm_grid, 256>>>(hA, tx1, p2, Wp0 + 3 * 4096,
                                        b + FDIM, hA, hB);

    // ---- layer 2: inp = hB -> d_out (skip = hB) ----
    pull_kernel<<<pull_grid, 256>>>(hB, tx1);
    pull_kernel<<<pull_grid, 256>>>(tx1, p2);
    gemm_epi_kernel<<<gemm_grid, 256>>>(hB, tx1, p2, Wp0 + 6 * 4096,
                                        b + 2 * FDIM, hB, out);
}

// round 7
// speedup vs baseline: 1.1013x; 1.0457x over previous
#include <cuda_runtime.h>
#include <cuda_fp16.h>

#define N_NODES 100000
#define N_EDGES 1200000
#define FDIM 64
#define NB_SCAN ((N_NODES + 1023) / 1024)   // 98

// ---------------- scratch (device globals; no allocation allowed) -------------
__device__ int    g_is64;
__device__ int    g_degs[N_NODES];
__device__ int    g_degd[N_NODES];
__device__ int    g_rowptr[N_NODES + 1];
__device__ int    g_cursor[N_NODES];
__device__ int    g_bsum[NB_SCAN];
__device__ int2   g_edge[N_EDGES];           // (src, norm-as-int) grouped by dst
__device__ __half g_xh [N_NODES * FDIM];     // fp16 gather copies
__device__ __half g_t1h[N_NODES * FDIM];
__device__ __half g_p2h[N_NODES * FDIM];
__device__ __half g_hAh[N_NODES * FDIM];
__device__ __half g_hBh[N_NODES * FDIM];
__device__ float  g_hA32[N_NODES * FDIM];    // fp32 for GEMM t0 + skip
__device__ float  g_hB32[N_NODES * FDIM];
__device__ float  g_Wp[3][3 * FDIM * FDIM];

// ---------------- init: zero degrees + dtype detection ------------------------
__global__ void init_kernel(const int* __restrict__ ei32) {
    int i = blockIdx.x * blockDim.x + threadIdx.x;
    if (i < N_NODES) { g_degs[i] = 0; g_degd[i] = 0; }
    if (i == 0) {
        int odd_zero = 1;
        for (int k = 0; k < 512; k++)
            if (ei32[2 * k + 1] != 0) { odd_zero = 0; break; }
        g_is64 = odd_zero;
    }
}

__device__ __forceinline__ void load_edge(const void* ei, int e, int& s, int& d) {
    if (g_is64) {
        const long long* p = (const long long*)ei;
        s = (int)p[e]; d = (int)p[N_EDGES + e];
    } else {
        const int* p = (const int*)ei;
        s = p[e]; d = p[N_EDGES + e];
    }
    if ((unsigned)s >= N_NODES || (unsigned)d >= N_NODES) { s = 0; d = 0; }
}

__global__ void count_kernel(const void* __restrict__ ei) {
    int e = blockIdx.x * blockDim.x + threadIdx.x;
    if (e >= N_EDGES) return;
    int s, d;
    load_edge(ei, e, s, d);
    atomicAdd(&g_degs[s], 1);
    atomicAdd(&g_degd[d], 1);
}

// ---- CSR build ---------------------------------------------------------------
__global__ __launch_bounds__(1024) void scan1_kernel() {
    __shared__ int s[1024];
    int tid = threadIdx.x;
    int i = blockIdx.x * 1024 + tid;
    int v = (i < N_NODES) ? g_degd[i] : 0;
    s[tid] = v;
    __syncthreads();
    for (int off = 1; off < 1024; off <<= 1) {
        int t = (tid >= off) ? s[tid - off] : 0;
        __syncthreads();
        s[tid] += t;
        __syncthreads();
    }
    int incl = s[tid];
    if (i < N_NODES) g_rowptr[i] = incl - v;
    if (tid == 1023) g_bsum[blockIdx.x] = incl;
}

__global__ __launch_bounds__(128) void scan2_kernel() {
    __shared__ int sh[128];
    int tid = threadIdx.x;
    int v = (tid < NB_SCAN) ? g_bsum[tid] : 0;
    sh[tid] = v;
    __syncthreads();
    for (int off = 1; off < 128; off <<= 1) {
        int t = (tid >= off) ? sh[tid - off] : 0;
        __syncthreads();
        sh[tid] += t;
        __syncthreads();
    }
    if (tid < NB_SCAN) g_bsum[tid] = sh[tid] - v;
    if (tid == 0) g_rowptr[N_NODES] = N_EDGES;
}

__global__ void scan3_kernel() {
    int i = blockIdx.x * blockDim.x + threadIdx.x;
    if (i >= N_NODES) return;
    int v = g_rowptr[i] + g_bsum[i >> 10];
    g_rowptr[i] = v;
    g_cursor[i] = v;
}

__global__ void fill_kernel(const void* __restrict__ ei) {
    int e = blockIdx.x * blockDim.x + threadIdx.x;
    if (e >= N_EDGES) return;
    int s, d;
    load_edge(ei, e, s, d);
    int pos = atomicAdd(&g_cursor[d], 1);
    int pd = g_degs[s] * g_degs[d];
    float nv = (pd > 0) ? -rsqrtf((float)pd) : 0.0f;
    g_edge[pos] = make_int2(s, __float_as_int(nv));
}

// ---- weight pre-transform: W0' = W0 - W2, W1' = W1, W2' = 2*W2 --------------
__global__ void wprep_kernel(const float* __restrict__ W) {
    int i = blockIdx.x * blockDim.x + threadIdx.x;
    if (i >= 3 * 3 * 4096) return;
    int layer = i / 12288, rem = i % 12288;
    int t = rem / 4096, idx = rem % 4096;
    const float* Wl = W + layer * 12288;
    float v;
    if (t == 0)      v = Wl[idx] - Wl[2 * 4096 + idx];
    else if (t == 1) v = Wl[4096 + idx];
    else             v = 2.0f * Wl[2 * 4096 + idx];
    g_Wp[layer][t * 4096 + idx] = v;
}

// ---- x -> fp16 copy ----------------------------------------------------------
__global__ void x2h_kernel(const float* __restrict__ x) {
    int i = blockIdx.x * blockDim.x + threadIdx.x;   // float4 index
    if (i >= N_NODES * FDIM / 4) return;
    float4 v = __ldg((const float4*)x + i);
    __half2 h0 = __floats2half2_rn(v.x, v.y);
    __half2 h1 = __floats2half2_rn(v.z, v.w);
    uint2 pk;
    pk.x = *(unsigned int*)&h0;
    pk.y = *(unsigned int*)&h1;
    ((uint2*)g_xh)[i] = pk;
}

// ---------------- pull-mode propagate over fp16 rows --------------------------
// 8 lanes per node, each lane loads 8 halves (16B) per edge; fp32 accumulate,
// fp16 store. Software-pipelined 4-edge batches; predicated lanes, no tail.
__global__ __launch_bounds__(256) void pull_kernel(const __half* __restrict__ in,
                                                   __half* __restrict__ out) {
    int t = blockIdx.x * 256 + threadIdx.x;
    int node = t >> 3;
    int lane = t & 7;
    if (node >= N_NODES) return;
    int e   = __ldg(&g_rowptr[node]);
    int end = __ldg(&g_rowptr[node + 1]);
    float acc[8];
#pragma unroll
    for (int j = 0; j < 8; j++) acc[j] = 0.f;

    if (e < end) {
        int2 ed[4];
        int last = end - 1;
#pragma unroll
        for (int i = 0; i < 4; i++)
            ed[i] = __ldg(&g_edge[min(e + i, last)]);

        while (true) {
            float n[4];
            uint4 v[4];
#pragma unroll
            for (int i = 0; i < 4; i++) {
                bool valid = (e + i < end);
                n[i] = valid ? __int_as_float(ed[i].y) : 0.f;
                int src = valid ? ed[i].x : 0;
                v[i] = __ldg((const uint4*)(in + src * FDIM + lane * 8));
            }
            int enext = e + 4;
            int2 ed2[4];
            bool more = (enext < end);
            if (more) {
#pragma unroll
                for (int i = 0; i < 4; i++)
                    ed2[i] = __ldg(&g_edge[min(enext + i, last)]);
            }
#pragma unroll
            for (int i = 0; i < 4; i++) {
                const __half2* hp = (const __half2*)&v[i];
#pragma unroll
                for (int j = 0; j < 4; j++) {
                    float2 f = __half22float2(hp[j]);
                    acc[2 * j]     = fmaf(n[i], f.x, acc[2 * j]);
                    acc[2 * j + 1] = fmaf(n[i], f.y, acc[2 * j + 1]);
                }
            }
            if (!more) break;
            e = enext;
#pragma unroll
            for (int i = 0; i < 4; i++) ed[i] = ed2[i];
        }
    }
    uint4 pk;
    __half2 h0 = __floats2half2_rn(acc[0], acc[1]);
    __half2 h1 = __floats2half2_rn(acc[2], acc[3]);
    __half2 h2 = __floats2half2_rn(acc[4], acc[5]);
    __half2 h3 = __floats2half2_rn(acc[6], acc[7]);
    pk.x = *(unsigned int*)&h0; pk.y = *(unsigned int*)&h1;
    pk.z = *(unsigned int*)&h2; pk.w = *(unsigned int*)&h3;
    *(uint4*)(out + node * FDIM + lane * 8) = pk;
}

// ---------------- fused 3-way GEMM (FFMA2, 2 rows/thread) --------------------
// out32[r] = t0[r]*W0' + t1h[r]*W1' + p2h[r]*W2' + bias (+skip32), relu
// optional fp16 copy of the output for the next layer's gather.
__device__ __forceinline__ void fma2(unsigned long long& acc,
                                     unsigned long long w,
                                     unsigned long long a) {
    asm("fma.rn.f32x2 %0, %1, %2, %0;" : "+l"(acc) : "l"(w), "l"(a));
}
__device__ __forceinline__ unsigned long long splat2(float f) {
    unsigned long long r;
    asm("mov.b64 %0, {%1, %1};" : "=l"(r) : "f"(f));
    return r;
}
__device__ __forceinline__ void h4_to_f4(uint2 u, float* f) {
    float2 lo = __half22float2(*(__half2*)&u.x);
    float2 hi = __half22float2(*(__half2*)&u.y);
    f[0] = lo.x; f[1] = lo.y; f[2] = hi.x; f[3] = hi.y;
}

__global__ __launch_bounds__(256) void gemm_epi_kernel(
    const float* __restrict__ t0, const __half* __restrict__ t1h,
    const __half* __restrict__ p2h, const float* __restrict__ Wp,
    const float* __restrict__ bias, const float* __restrict__ skip,
    float* __restrict__ out32, __half* __restrict__ outh) {
    __shared__ float sW[3 * FDIM * FDIM];  // 48 KB

    for (int i = threadIdx.x; i < 3 * FDIM * FDIM / 4; i += 256)
        ((float4*)sW)[i] = ((const float4*)Wp)[i];
    __syncthreads();

    int base = blockIdx.x * 128;
    int rg = threadIdx.x >> 2;
    int q  = threadIdx.x & 3;
    int jb = q * 16;
    int rA = base + rg;
    int rB = base + rg + 64;
    bool okA = rA < N_NODES, okB = rB < N_NODES;
    if (!okA) return;

    unsigned long long accA[8], accB[8];
#pragma unroll
    for (int i = 0; i < 8; i++) { accA[i] = 0ULL; accB[i] = 0ULL; }

#pragma unroll 2
    for (int kk = 0; kk < FDIM; kk += 4) {
        float4 xa0 = __ldg((const float4*)(t0 + rA * FDIM + kk));
        uint2  ua1 = __ldg((const uint2*)(t1h + rA * FDIM + kk));
        uint2  ua2 = __ldg((const uint2*)(p2h + rA * FDIM + kk));
        float4 xb0 = make_float4(0.f, 0.f, 0.f, 0.f);
        uint2  ub1 = make_uint2(0u, 0u), ub2 = make_uint2(0u, 0u);
        if (okB) {
            xb0 = __ldg((const float4*)(t0 + rB * FDIM + kk));
            ub1 = __ldg((const uint2*)(t1h + rB * FDIM + kk));
            ub2 = __ldg((const uint2*)(p2h + rB * FDIM + kk));
        }
        float fa0[4] = {xa0.x, xa0.y, xa0.z, xa0.w};
        float fb0[4] = {xb0.x, xb0.y, xb0.z, xb0.w};
        float fa1[4], fa2[4], fb1[4], fb2[4];
        h4_to_f4(ua1, fa1); h4_to_f4(ua2, fa2);
        h4_to_f4(ub1, fb1); h4_to_f4(ub2, fb2);
#pragma unroll
        for (int u = 0; u < 4; u++) {
            int k = kk + u;
            const ulonglong2* w0 = (const ulonglong2*)(sW + k * FDIM + jb);
            const ulonglong2* w1 = (const ulonglong2*)(sW + 4096 + k * FDIM + jb);
            const ulonglong2* w2 = (const ulonglong2*)(sW + 8192 + k * FDIM + jb);
            {
                unsigned long long sA = splat2(fa0[u]), sB = splat2(fb0[u]);
#pragma unroll
                for (int p = 0; p < 4; p++) {
                    ulonglong2 w = w0[p];
                    fma2(accA[2 * p], w.x, sA); fma2(accA[2 * p + 1], w.y, sA);
                    fma2(accB[2 * p], w.x, sB); fma2(accB[2 * p + 1], w.y, sB);
                }
            }
            {
                unsigned long long sA = splat2(fa1[u]), sB = splat2(fb1[u]);
#pragma unroll
                for (int p = 0; p < 4; p++) {
                    ulonglong2 w = w1[p];
                    fma2(accA[2 * p], w.x, sA); fma2(accA[2 * p + 1], w.y, sA);
                    fma2(accB[2 * p], w.x, sB); fma2(accB[2 * p + 1], w.y, sB);
                }
            }
            {
                unsigned long long sA = splat2(fa2[u]), sB = splat2(fb2[u]);
#pragma unroll
                for (int p = 0; p < 4; p++) {
                    ulonglong2 w = w2[p];
                    fma2(accA[2 * p], w.x, sA); fma2(accA[2 * p + 1], w.y, sA);
                    fma2(accB[2 * p], w.x, sB); fma2(accB[2 * p + 1], w.y, sB);
                }
            }
        }
    }

    float bia[16];
#pragma unroll
    for (int j = 0; j < 16; j++) bia[j] = bias[jb + j];

#pragma unroll
    for (int rr = 0; rr < 2; rr++) {
        int r = rr ? rB : rA;
        if (rr && !okB) break;
        unsigned long long* acc = rr ? accB : accA;
        float o[16];
#pragma unroll
        for (int i = 0; i < 8; i++) {
            float f0, f1;
            asm("mov.b64 {%0, %1}, %2;" : "=f"(f0), "=f"(f1) : "l"(acc[i]));
            o[2 * i] = f0; o[2 * i + 1] = f1;
        }
#pragma unroll
        for (int j = 0; j < 16; j++) {
            float v = o[j] + bia[j];
            if (skip) v += skip[r * FDIM + jb + j];
            o[j] = fmaxf(v, 0.f);
        }
#pragma unroll
        for (int p = 0; p < 4; p++)
            *(float4*)(out32 + r * FDIM + jb + 4 * p) =
                make_float4(o[4*p], o[4*p+1], o[4*p+2], o[4*p+3]);
        if (outh) {
#pragma unroll
            for (int p = 0; p < 2; p++) {
                uint4 pk;
                __half2 h0 = __floats2half2_rn(o[8*p+0], o[8*p+1]);
                __half2 h1 = __floats2half2_rn(o[8*p+2], o[8*p+3]);
                __half2 h2 = __floats2half2_rn(o[8*p+4], o[8*p+5]);
                __half2 h3 = __floats2half2_rn(o[8*p+6], o[8*p+7]);
                pk.x = *(unsigned int*)&h0; pk.y = *(unsigned int*)&h1;
                pk.z = *(unsigned int*)&h2; pk.w = *(unsigned int*)&h3;
                *(uint4*)(outh + r * FDIM + jb + 8 * p) = pk;
            }
        }
    }
}

// ---------------- launch orchestration ---------------------------------------
static inline int cdiv(long long a, long long b) { return (int)((a + b - 1) / b); }

extern "C" void kernel_launch(void* const* d_in, const int* in_sizes, int n_in,
                              void* d_out, int out_size) {
    const float* x  = (const float*)d_in[0];
    const void*  ei = d_in[1];
    const float* W  = (const float*)d_in[2];
    const float* b  = (const float*)d_in[3];
    float*       out = (float*)d_out;

    __half *xh, *t1h, *p2h, *hAh, *hBh;
    float  *hA32, *hB32, *Wp0;
    cudaGetSymbolAddress((void**)&xh,   g_xh);
    cudaGetSymbolAddress((void**)&t1h,  g_t1h);
    cudaGetSymbolAddress((void**)&p2h,  g_p2h);
    cudaGetSymbolAddress((void**)&hAh,  g_hAh);
    cudaGetSymbolAddress((void**)&hBh,  g_hBh);
    cudaGetSymbolAddress((void**)&hA32, g_hA32);
    cudaGetSymbolAddress((void**)&hB32, g_hB32);
    cudaGetSymbolAddress((void**)&Wp0,  g_Wp);

    // ---- graph prep ----
    init_kernel<<<cdiv(N_NODES, 256), 256>>>((const int*)ei);
    count_kernel<<<cdiv(N_EDGES, 256), 256>>>(ei);
    scan1_kernel<<<NB_SCAN, 1024>>>();
    scan2_kernel<<<1, 128>>>();
    scan3_kernel<<<cdiv(N_NODES, 256), 256>>>();
    fill_kernel<<<cdiv(N_EDGES, 256), 256>>>(ei);
    wprep_kernel<<<cdiv(3 * 3 * 4096, 256), 256>>>(W);
    x2h_kernel<<<cdiv(N_NODES * FDIM / 4, 256), 256>>>(x);

    const int pull_grid = cdiv((long long)N_NODES * 8, 256);
    const int gemm_grid = cdiv(N_NODES, 128);

    // ---- layer 0: t0 = x (fp32), gathers over xh ----
    pull_kernel<<<pull_grid, 256>>>(xh, t1h);
    pull_kernel<<<pull_grid, 256>>>(t1h, p2h);
    gemm_epi_kernel<<<gemm_grid, 256>>>(x, t1h, p2h, Wp0, b, nullptr,
                                        hA32, hAh);

    // ---- layer 1 ----
    pull_kernel<<<pull_grid, 256>>>(hAh, t1h);
    pull_kernel<<<pull_grid, 256>>>(t1h, p2h);
    gemm_epi_kernel<<<gemm_grid, 256>>>(hA32, t1h, p2h, Wp0 + 3 * 4096,
                                        b + FDIM, hA32, hB32, hBh);

    // ---- layer 2 ----
    pull_kernel<<<pull_grid, 256>>>(hBh, t1h);
    pull_kernel<<<pull_grid, 256>>>(t1h, p2h);
    gemm_epi_kernel<<<gemm_grid, 256>>>(hB32, t1h, p2h, Wp0 + 6 * 4096,
                                        b + 2 * FDIM, hB32, out, nullptr);
}